// round 15
// baseline (speedup 1.0000x reference)
#include <cuda_runtime.h>
#include <cuda_fp16.h>
#include <cstdint>

// ---------------- problem constants ----------------
#define BB   16
#define TT   34
#define TP   32          // T - DIL
#define NN   1000
#define CIN  32
#define DC   32
#define OC   64
#define EE   16000
#define NNZ  (EE + NN)   // edges + self loops = 17000
#define GG   (BB * TP)   // 512 graphs
#define NB   4           // nodes per k_gate block

#define OUT1_ELEMS ((size_t)BB * DC * NN * TP)        // 16,384,000

typedef unsigned long long u64c;

// ---------------- f32x2 packed helpers ----------------
__device__ __forceinline__ u64c fma2(u64c a, u64c b, u64c c) {
    u64c d;
    asm("fma.rn.f32x2 %0, %1, %2, %3;" : "=l"(d) : "l"(a), "l"(b), "l"(c));
    return d;
}
__device__ __forceinline__ u64c add2(u64c a, u64c b) {
    u64c d;
    asm("add.rn.f32x2 %0, %1, %2;" : "=l"(d) : "l"(a), "l"(b));
    return d;
}
__device__ __forceinline__ float f2sum(u64c a) {
    return __int_as_float((int)(a & 0xffffffffULL)) +
           __int_as_float((int)(a >> 32));
}
__device__ __forceinline__ u64c pack2(float lo, float hi) {
    u64c r;
    asm("mov.b64 %0, {%1, %2};" : "=l"(r) : "f"(lo), "f"(hi));
    return r;
}
__device__ __forceinline__ float u64lo(u64c a) { return __int_as_float((int)(a & 0xffffffffULL)); }
__device__ __forceinline__ float u64hi(u64c a) { return __int_as_float((int)(a >> 32)); }
// half2 (as uint) -> packed f32x2
__device__ __forceinline__ u64c h2tof2(unsigned int h) {
    __half2 hv = *(__half2*)&h;
    float2 f = __half22float2(hv);
    u64c r;
    asm("mov.b64 %0, {%1, %2};" : "=l"(r) : "f"(f.x), "f"(f.y));
    return r;
}

// ---------------- device scratch ----------------
__device__ __half g_zh[(size_t)GG * NN * OC];  // 65.5 MB: z = gated @ Wcomb^T (fp16)
__device__ float  g_wcomb[OC * DC];            // Wcomb[o][d] = sum_c wout[o][c] wgcn[c][d]
__device__ float  g_ybias[OC];                 // bgcn @ wout^T + bout
__device__ int    g_off[NN + 1];
__device__ int2   g_csr[NNZ];                  // (src*128 byte offset, f32 val as int)

// ---------------- K_comb: combined weights + ybias --------------------------
__global__ void k_comb(const float* __restrict__ wgcn, const float* __restrict__ bgcn,
                       const float* __restrict__ wout, const float* __restrict__ bout) {
    __shared__ float sg[CIN * DC];   // wgcn [c][d]
    __shared__ float so[OC * CIN];   // wout [o][c]
    __shared__ float sb[CIN];
    int tid = threadIdx.x;
    for (int f = tid; f < CIN * DC; f += blockDim.x) sg[f] = wgcn[f];
    for (int f = tid; f < OC * CIN; f += blockDim.x) so[f] = wout[f];
    if (tid < CIN) sb[tid] = bgcn[tid];
    __syncthreads();
    for (int f = tid; f < OC * DC; f += blockDim.x) {
        int o = f >> 5, d = f & 31;
        float s = 0.f;
#pragma unroll
        for (int c = 0; c < CIN; c++) s += so[o * CIN + c] * sg[c * DC + d];
        g_wcomb[f] = s;
    }
    if (tid < OC) {
        float s = bout[tid];
#pragma unroll
        for (int c = 0; c < CIN; c++) s += sb[c] * so[tid * CIN + c];
        g_ybias[tid] = s;
    }
}

// ---------------- K_build: fused CSR build (single block, smem atomics) ----
__global__ __launch_bounds__(1024) void k_build(const int* __restrict__ ei,
                                                const float* __restrict__ ew) {
    __shared__ float sdeg[NN];
    __shared__ int   scnt[NN];
    __shared__ int   ssc[1024];
    __shared__ int   scur[NN];
    int tid = threadIdx.x;

    for (int i = tid; i < NN; i += 1024) { sdeg[i] = 0.f; scnt[i] = 0; }
    __syncthreads();

    for (int i = tid; i < NNZ; i += 1024) {
        int d; float w;
        if (i < EE) { d = ei[EE + i]; w = ew[i]; }
        else        { d = i - EE;     w = 1.f;   }
        atomicAdd(&sdeg[d], w);
        atomicAdd(&scnt[d], 1);
    }
    __syncthreads();

    int v = (tid < NN) ? scnt[tid] : 0;
    ssc[tid] = v;
    __syncthreads();
    for (int off = 1; off < 1024; off <<= 1) {
        int tv = (tid >= off) ? ssc[tid - off] : 0;
        __syncthreads();
        ssc[tid] += tv;
        __syncthreads();
    }
    if (tid < NN) {
        int excl = ssc[tid] - v;
        scur[tid] = excl;
        g_off[tid] = excl;
    }
    if (tid == NN - 1) g_off[NN] = ssc[tid];
    __syncthreads();

    for (int i = tid; i < NNZ; i += 1024) {
        int s, d; float w;
        if (i < EE) { s = ei[i]; d = ei[EE + i]; w = ew[i]; }
        else        { s = i - EE; d = s;         w = 1.f;   }
        float degs = sdeg[s], degd = sdeg[d];
        float dis_s = (degs > 0.f) ? rsqrtf(degs) : 0.f;
        float dis_d = (degd > 0.f) ? rsqrtf(degd) : 0.f;
        int p = atomicAdd(&scur[d], 1);
        // fp16 slab row pitch = 64 ch * 2B = 128 B
        g_csr[p] = make_int2(s * 128, __float_as_int(dis_s * w * dis_d));
    }
}

// ---------------- K_gate: fused gated conv + z, NB=4 nodes per block -------
// (R13 structure, the 403us best.) Phase 1: warp wy owns o-quad, t = lane,
// NB-node weight reuse, fp32 weights, packed fma2; gated stored to smem as
// half2 (STS.64) and to out1 exact fp32. Phase 2: thread (o=tid&63, ts=tid>>6)
// reads gs via LDS.64 broadcasts, Wcomb row in regs, fp16 z stores.
// __launch_bounds__(256,2) caps regs at 128 -> 2 blocks/SM.
#define GSP 18   // gs pitch in half2 units (36 halves = 72B per t-row)
struct SmemGate {
    float4 xq[NB][8][34];                  // [nb][c4][t]
    float4 w1a[32][8], w1b[32][8];         // [o][c4]
    float4 w2a[32][8], w2b[32][8];
    float4 wcq[8][64];                     // [d4][o] = Wcomb[o][4d4..4d4+3]
    unsigned int gs[NB][32 * GSP];         // gated [t][d-pairs] as half2
};

__global__ __launch_bounds__(256, 2) void k_gate(
    const float* __restrict__ x,
    const float* __restrict__ wg1, const float* __restrict__ bg1,
    const float* __restrict__ wg2, const float* __restrict__ bg2,
    float* __restrict__ out1)
{
    extern __shared__ char smem_raw[];
    SmemGate& S = *(SmemGate*)smem_raw;

    int blk = blockIdx.x;                  // 4000 blocks
    int b  = blk / (NN / NB);
    int n0 = (blk - b * (NN / NB)) * NB;

    int tx = threadIdx.x;                  // 0..31 (t)
    int wy = threadIdx.y;                  // 0..7  (o-quad)
    int tid = wy * 32 + tx;

    // stage gate weights (flat f = o*32+c, 1024 per array)
    for (int f = tid; f < 32 * 32; f += 256) {
        float2 v1 = *(const float2*)(wg1 + f * 2);
        float2 v2 = *(const float2*)(wg2 + f * 2);
        ((float*)S.w1a)[f] = v1.x;
        ((float*)S.w1b)[f] = v1.y;
        ((float*)S.w2a)[f] = v2.x;
        ((float*)S.w2b)[f] = v2.y;
    }
    // stage Wcomb: flat f = (d4*64+o)*4+k  <-  wcomb[o*32 + d4*4 + k]
    for (int f = tid; f < 8 * 64 * 4; f += 256) {
        int k = f & 3, o = (f >> 2) & 63, d4 = f >> 8;
        ((float*)S.wcq)[f] = g_wcomb[o * 32 + d4 * 4 + k];
    }
    // stage x tiles: NB nodes x 34 t x 8 c4
    for (int f = tid; f < NB * 34 * 8; f += 256) {
        int nb = f / (34 * 8);
        int r  = f - nb * (34 * 8);
        int t = r >> 3, c4 = r & 7;
        S.xq[nb][c4][t] =
            *(const float4*)(x + ((size_t)(b * TT + t) * NN + (n0 + nb)) * CIN + c4 * 4);
    }
    __syncthreads();

    // ---- phase 1: gates ----
    {
        float bg1v[4], bg2v[4];
#pragma unroll
        for (int oo = 0; oo < 4; oo++) {
            bg1v[oo] = __ldg(bg1 + 4 * wy + oo);
            bg2v[oo] = __ldg(bg2 + 4 * wy + oo);
        }
        u64c a1[4][NB], a2[4][NB];
#pragma unroll
        for (int oo = 0; oo < 4; oo++)
#pragma unroll
            for (int nb = 0; nb < NB; nb++) { a1[oo][nb] = 0; a2[oo][nb] = 0; }

#pragma unroll
        for (int c4 = 0; c4 < 8; c4++) {
            ulonglong2 xa[NB], xb[NB];
#pragma unroll
            for (int nb = 0; nb < NB; nb++) {
                xa[nb] = *(const ulonglong2*)&S.xq[nb][c4][tx];
                xb[nb] = *(const ulonglong2*)&S.xq[nb][c4][tx + 2];
            }
#pragma unroll
            for (int oo = 0; oo < 4; oo++) {
                int o = 4 * wy + oo;
                ulonglong2 A1 = *(const ulonglong2*)&S.w1a[o][c4];
                ulonglong2 B1 = *(const ulonglong2*)&S.w1b[o][c4];
                ulonglong2 A2 = *(const ulonglong2*)&S.w2a[o][c4];
                ulonglong2 B2 = *(const ulonglong2*)&S.w2b[o][c4];
#pragma unroll
                for (int nb = 0; nb < NB; nb++) {
                    a1[oo][nb] = fma2(xa[nb].x, A1.x, a1[oo][nb]);
                    a1[oo][nb] = fma2(xa[nb].y, A1.y, a1[oo][nb]);
                    a1[oo][nb] = fma2(xb[nb].x, B1.x, a1[oo][nb]);
                    a1[oo][nb] = fma2(xb[nb].y, B1.y, a1[oo][nb]);
                    a2[oo][nb] = fma2(xa[nb].x, A2.x, a2[oo][nb]);
                    a2[oo][nb] = fma2(xa[nb].y, A2.y, a2[oo][nb]);
                    a2[oo][nb] = fma2(xb[nb].x, B2.x, a2[oo][nb]);
                    a2[oo][nb] = fma2(xb[nb].y, B2.y, a2[oo][nb]);
                }
            }
        }

#pragma unroll
        for (int nb = 0; nb < NB; nb++) {
            float4 gq;
#pragma unroll
            for (int oo = 0; oo < 4; oo++) {
                int o = 4 * wy + oo;
                float s1 = f2sum(a1[oo][nb]) + bg1v[oo];
                float s2 = f2sum(a2[oo][nb]) + bg2v[oo];
                float e1 = __expf(2.f * s1);
                float th = 1.f - __fdividef(2.f, e1 + 1.f);    // tanh, inf-safe
                float sg = __fdividef(1.f, 1.f + __expf(-s2)); // sigmoid
                float gated = th * sg;
                out1[((size_t)(b * DC + o) * NN + (n0 + nb)) * TP + tx] = gated;
                (&gq.x)[oo] = gated;
            }
            __half2 h0 = __floats2half2_rn(gq.x, gq.y);
            __half2 h1 = __floats2half2_rn(gq.z, gq.w);
            uint2 hp;
            hp.x = *(unsigned int*)&h0;
            hp.y = *(unsigned int*)&h1;
            *(uint2*)&S.gs[nb][tx * GSP + wy * 2] = hp;
        }
    }
    __syncthreads();

    // ---- phase 2: z[t][o] = sum_d gated[t][d] * Wcomb[o][d]  (fp16 in/out) --
    {
        int o  = tid & 63;
        int ts = tid >> 6;          // 0..3
        ulonglong2 wr[8];
#pragma unroll
        for (int d4 = 0; d4 < 8; d4++)
            wr[d4] = *(const ulonglong2*)&S.wcq[d4][o];
#pragma unroll
        for (int nb = 0; nb < NB; nb++) {
            const unsigned int* gsn = S.gs[nb];
#pragma unroll
            for (int it = 0; it < 8; it++) {
                int t = ts * 8 + it;
                u64c za = 0, zb = 0;
#pragma unroll
                for (int d4 = 0; d4 < 8; d4++) {
                    uint2 gg = *(const uint2*)&gsn[t * GSP + d4 * 2];  // LDS.64 bcast
                    za = fma2(h2tof2(gg.x), wr[d4].x, za);
                    zb = fma2(h2tof2(gg.y), wr[d4].y, zb);
                }
                g_zh[((size_t)(b * TP + t) * NN + (n0 + nb)) * OC + o] =
                    __float2half(f2sum(za) + f2sum(zb));
            }
        }
    }
}

// ---------------- K_spmm: gather over fp16 z, ONE ROW PER WARP --------------
// 512 blocks (one per graph). z slab (1000x64 half = 128 KB) staged in dynamic
// SMEM. Warp processes one row at a time: sub = lane>>3 picks edge e+sub
// (4 edges in flight, MLP-4, zero divergence), l8 = lane&7 the channel octet.
// Cross-sub combine via shfl.xor(8,16) + add2 at row end; bias added after.
__global__ __launch_bounds__(1024, 1) void k_spmm(float* __restrict__ y)
{
    extern __shared__ char z_raw[];           // [N][64] halves, 128 B rows
    int g   = blockIdx.x;
    int tid = threadIdx.x;

    {
        const uint4* src = (const uint4*)(g_zh + (size_t)g * NN * OC);
        uint4* dst = (uint4*)z_raw;
        for (int f = tid; f < NN * OC / 8; f += 1024)
            dst[f] = src[f];
    }
    __syncthreads();

    int lane = tid & 31;
    int sub  = lane >> 3;                     // edge slot within 4-edge batch
    int l8   = lane & 7;                      // channel octet
    int o0   = l8 * 8;
    int warp = tid >> 5;

    float4 yb0 = *(const float4*)(g_ybias + o0);
    float4 yb1 = *(const float4*)(g_ybias + o0 + 4);
    const char* zb = z_raw + l8 * 16;

    for (int i = warp; i < NN; i += 32) {
        int r0 = g_off[i], r1 = g_off[i + 1];

        u64c a0 = 0, a1 = 0, a2 = 0, a3 = 0;
        for (int e = r0 + sub; e < r1; e += 4) {
            int2 ev = __ldg(&g_csr[e]);       // uniform within 8-lane group
            uint4 zz = *(const uint4*)(zb + ev.x);
            float vf = __int_as_float(ev.y);
            u64c vv = pack2(vf, vf);
            a0 = fma2(h2tof2(zz.x), vv, a0);
            a1 = fma2(h2tof2(zz.y), vv, a1);
            a2 = fma2(h2tof2(zz.z), vv, a2);
            a3 = fma2(h2tof2(zz.w), vv, a3);
        }
        // combine the 4 edge-slot partials (lanes differing in bits 3,4)
        a0 = add2(a0, __shfl_xor_sync(0xffffffffu, a0, 8));
        a1 = add2(a1, __shfl_xor_sync(0xffffffffu, a1, 8));
        a2 = add2(a2, __shfl_xor_sync(0xffffffffu, a2, 8));
        a3 = add2(a3, __shfl_xor_sync(0xffffffffu, a3, 8));
        a0 = add2(a0, __shfl_xor_sync(0xffffffffu, a0, 16));
        a1 = add2(a1, __shfl_xor_sync(0xffffffffu, a1, 16));
        a2 = add2(a2, __shfl_xor_sync(0xffffffffu, a2, 16));
        a3 = add2(a3, __shfl_xor_sync(0xffffffffu, a3, 16));

        if (sub == 0) {
            float* yo = y + ((size_t)g * NN + i) * OC + o0;
            float4 r0v, r1v;
            r0v.x = u64lo(a0) + yb0.x; r0v.y = u64hi(a0) + yb0.y;
            r0v.z = u64lo(a1) + yb0.z; r0v.w = u64hi(a1) + yb0.w;
            r1v.x = u64lo(a2) + yb1.x; r1v.y = u64hi(a2) + yb1.y;
            r1v.z = u64lo(a3) + yb1.z; r1v.w = u64hi(a3) + yb1.w;
            *(float4*)yo       = r0v;
            *(float4*)(yo + 4) = r1v;
        }
    }
}

// ---------------- launcher ----------------
extern "C" void kernel_launch(void* const* d_in, const int* in_sizes, int n_in,
                              void* d_out, int out_size)
{
    const float* x    = (const float*)d_in[0];
    const int*   ei   = (const int*)  d_in[1];
    const float* ew   = (const float*)d_in[2];
    const float* wg1  = (const float*)d_in[3];
    const float* bg1  = (const float*)d_in[4];
    const float* wg2  = (const float*)d_in[5];
    const float* bg2  = (const float*)d_in[6];
    const float* wgcn = (const float*)d_in[7];
    const float* bgcn = (const float*)d_in[8];
    const float* wout = (const float*)d_in[9];
    const float* bout = (const float*)d_in[10];
    float* out = (float*)d_out;

    // 4 launches: k_spmm is launch #4 (ncu capture slot)
    k_comb <<<1, 512>>>(wgcn, bgcn, wout, bout);
    k_build<<<1, 1024>>>(ei, ew);

    size_t gate_smem = sizeof(SmemGate);      // ~51 KB (2 blocks/SM)
    cudaFuncSetAttribute(k_gate, cudaFuncAttributeMaxDynamicSharedMemorySize,
                         (int)gate_smem);
    k_gate<<<BB * (NN / NB), dim3(32, 8), gate_smem>>>(x, wg1, bg1, wg2, bg2, out);

    size_t smem_bytes = (size_t)NN * OC * sizeof(__half);   // 128 KB
    cudaFuncSetAttribute(k_spmm, cudaFuncAttributeMaxDynamicSharedMemorySize,
                         (int)smem_bytes);
    k_spmm<<<GG, 1024, smem_bytes>>>(out + OUT1_ELEMS);
}

// round 16
// speedup vs baseline: 1.1170x; 1.1170x over previous
#include <cuda_runtime.h>
#include <cuda_fp16.h>
#include <cstdint>

// ---------------- problem constants ----------------
#define BB   16
#define TT   34
#define TP   32          // T - DIL
#define NN   1000
#define CIN  32
#define DC   32
#define OC   64
#define EE   16000
#define NNZ  (EE + NN)   // edges + self loops = 17000
#define GG   (BB * TP)   // 512 graphs
#define NB   4           // nodes per k_gate block

#define OUT1_ELEMS ((size_t)BB * DC * NN * TP)        // 16,384,000

typedef unsigned long long u64c;

// ---------------- f32x2 packed helpers ----------------
__device__ __forceinline__ u64c fma2(u64c a, u64c b, u64c c) {
    u64c d;
    asm("fma.rn.f32x2 %0, %1, %2, %3;" : "=l"(d) : "l"(a), "l"(b), "l"(c));
    return d;
}
__device__ __forceinline__ u64c add2(u64c a, u64c b) {
    u64c d;
    asm("add.rn.f32x2 %0, %1, %2;" : "=l"(d) : "l"(a), "l"(b));
    return d;
}
__device__ __forceinline__ float f2sum(u64c a) {
    return __int_as_float((int)(a & 0xffffffffULL)) +
           __int_as_float((int)(a >> 32));
}
__device__ __forceinline__ u64c pack2(float lo, float hi) {
    u64c r;
    asm("mov.b64 %0, {%1, %2};" : "=l"(r) : "f"(lo), "f"(hi));
    return r;
}
__device__ __forceinline__ float u64lo(u64c a) { return __int_as_float((int)(a & 0xffffffffULL)); }
__device__ __forceinline__ float u64hi(u64c a) { return __int_as_float((int)(a >> 32)); }
// half2 (as uint) -> packed f32x2
__device__ __forceinline__ u64c h2tof2(unsigned int h) {
    __half2 hv = *(__half2*)&h;
    float2 f = __half22float2(hv);
    u64c r;
    asm("mov.b64 %0, {%1, %2};" : "=l"(r) : "f"(f.x), "f"(f.y));
    return r;
}
// fp16x2 ops on uint-carried half2
__device__ __forceinline__ unsigned int hmul2u(unsigned int a, unsigned int b) {
    __half2 r = __hmul2(*(__half2*)&a, *(__half2*)&b);
    return *(unsigned int*)&r;
}
__device__ __forceinline__ unsigned int hfma2u(unsigned int a, unsigned int b, unsigned int c) {
    __half2 r = __hfma2(*(__half2*)&a, *(__half2*)&b, *(__half2*)&c);
    return *(unsigned int*)&r;
}

// ---------------- device scratch ----------------
__device__ __half g_zh[(size_t)GG * NN * OC];  // 65.5 MB: z = gated @ Wcomb^T (fp16)
__device__ float  g_wcomb[OC * DC];            // Wcomb[o][d] = sum_c wout[o][c] wgcn[c][d]
__device__ float  g_ybias[OC];                 // bgcn @ wout^T + bout
__device__ int    g_off[NN + 1];
__device__ int2   g_csr[NNZ];                  // (src*128 byte offset, half2(val,val))

// ---------------- K_comb: combined weights + ybias --------------------------
__global__ void k_comb(const float* __restrict__ wgcn, const float* __restrict__ bgcn,
                       const float* __restrict__ wout, const float* __restrict__ bout) {
    __shared__ float sg[CIN * DC];   // wgcn [c][d]
    __shared__ float so[OC * CIN];   // wout [o][c]
    __shared__ float sb[CIN];
    int tid = threadIdx.x;
    for (int f = tid; f < CIN * DC; f += blockDim.x) sg[f] = wgcn[f];
    for (int f = tid; f < OC * CIN; f += blockDim.x) so[f] = wout[f];
    if (tid < CIN) sb[tid] = bgcn[tid];
    __syncthreads();
    for (int f = tid; f < OC * DC; f += blockDim.x) {
        int o = f >> 5, d = f & 31;
        float s = 0.f;
#pragma unroll
        for (int c = 0; c < CIN; c++) s += so[o * CIN + c] * sg[c * DC + d];
        g_wcomb[f] = s;
    }
    if (tid < OC) {
        float s = bout[tid];
#pragma unroll
        for (int c = 0; c < CIN; c++) s += sb[c] * so[tid * CIN + c];
        g_ybias[tid] = s;
    }
}

// ---------------- K_build: fused CSR build (single block, smem atomics) ----
__global__ __launch_bounds__(1024) void k_build(const int* __restrict__ ei,
                                                const float* __restrict__ ew) {
    __shared__ float sdeg[NN];
    __shared__ int   scnt[NN];
    __shared__ int   ssc[1024];
    __shared__ int   scur[NN];
    int tid = threadIdx.x;

    for (int i = tid; i < NN; i += 1024) { sdeg[i] = 0.f; scnt[i] = 0; }
    __syncthreads();

    for (int i = tid; i < NNZ; i += 1024) {
        int d; float w;
        if (i < EE) { d = ei[EE + i]; w = ew[i]; }
        else        { d = i - EE;     w = 1.f;   }
        atomicAdd(&sdeg[d], w);
        atomicAdd(&scnt[d], 1);
    }
    __syncthreads();

    int v = (tid < NN) ? scnt[tid] : 0;
    ssc[tid] = v;
    __syncthreads();
    for (int off = 1; off < 1024; off <<= 1) {
        int tv = (tid >= off) ? ssc[tid - off] : 0;
        __syncthreads();
        ssc[tid] += tv;
        __syncthreads();
    }
    if (tid < NN) {
        int excl = ssc[tid] - v;
        scur[tid] = excl;
        g_off[tid] = excl;
    }
    if (tid == NN - 1) g_off[NN] = ssc[tid];
    __syncthreads();

    for (int i = tid; i < NNZ; i += 1024) {
        int s, d; float w;
        if (i < EE) { s = ei[i]; d = ei[EE + i]; w = ew[i]; }
        else        { s = i - EE; d = s;         w = 1.f;   }
        float degs = sdeg[s], degd = sdeg[d];
        float dis_s = (degs > 0.f) ? rsqrtf(degs) : 0.f;
        float dis_d = (degd > 0.f) ? rsqrtf(degd) : 0.f;
        float nrm = dis_s * w * dis_d;
        int p = atomicAdd(&scur[d], 1);
        // fp16 slab row pitch = 64 ch * 2B = 128 B; val pre-duplicated half2
        __half2 hv = __half2half2(__float2half_rn(nrm));
        g_csr[p] = make_int2(s * 128, *(int*)&hv);
    }
}

// ---------------- K_gate: fused gated conv + z, NB=4 nodes per block -------
// (R13 structure, the 403us best — unchanged.) Phase 1: warp wy owns o-quad,
// t = lane, NB-node weight reuse, fp32 weights, packed fma2; gated stored to
// smem as half2 (STS.64) and to out1 exact fp32. Phase 2: thread (o=tid&63,
// ts=tid>>6) reads gs via LDS.64 broadcasts, Wcomb row in regs, fp16 z stores.
#define GSP 18   // gs pitch in half2 units (36 halves = 72B per t-row)
struct SmemGate {
    float4 xq[NB][8][34];                  // [nb][c4][t]
    float4 w1a[32][8], w1b[32][8];         // [o][c4]
    float4 w2a[32][8], w2b[32][8];
    float4 wcq[8][64];                     // [d4][o] = Wcomb[o][4d4..4d4+3]
    unsigned int gs[NB][32 * GSP];         // gated [t][d-pairs] as half2
};

__global__ __launch_bounds__(256, 2) void k_gate(
    const float* __restrict__ x,
    const float* __restrict__ wg1, const float* __restrict__ bg1,
    const float* __restrict__ wg2, const float* __restrict__ bg2,
    float* __restrict__ out1)
{
    extern __shared__ char smem_raw[];
    SmemGate& S = *(SmemGate*)smem_raw;

    int blk = blockIdx.x;                  // 4000 blocks
    int b  = blk / (NN / NB);
    int n0 = (blk - b * (NN / NB)) * NB;

    int tx = threadIdx.x;                  // 0..31 (t)
    int wy = threadIdx.y;                  // 0..7  (o-quad)
    int tid = wy * 32 + tx;

    // stage gate weights (flat f = o*32+c, 1024 per array)
    for (int f = tid; f < 32 * 32; f += 256) {
        float2 v1 = *(const float2*)(wg1 + f * 2);
        float2 v2 = *(const float2*)(wg2 + f * 2);
        ((float*)S.w1a)[f] = v1.x;
        ((float*)S.w1b)[f] = v1.y;
        ((float*)S.w2a)[f] = v2.x;
        ((float*)S.w2b)[f] = v2.y;
    }
    // stage Wcomb: flat f = (d4*64+o)*4+k  <-  wcomb[o*32 + d4*4 + k]
    for (int f = tid; f < 8 * 64 * 4; f += 256) {
        int k = f & 3, o = (f >> 2) & 63, d4 = f >> 8;
        ((float*)S.wcq)[f] = g_wcomb[o * 32 + d4 * 4 + k];
    }
    // stage x tiles: NB nodes x 34 t x 8 c4
    for (int f = tid; f < NB * 34 * 8; f += 256) {
        int nb = f / (34 * 8);
        int r  = f - nb * (34 * 8);
        int t = r >> 3, c4 = r & 7;
        S.xq[nb][c4][t] =
            *(const float4*)(x + ((size_t)(b * TT + t) * NN + (n0 + nb)) * CIN + c4 * 4);
    }
    __syncthreads();

    // ---- phase 1: gates ----
    {
        float bg1v[4], bg2v[4];
#pragma unroll
        for (int oo = 0; oo < 4; oo++) {
            bg1v[oo] = __ldg(bg1 + 4 * wy + oo);
            bg2v[oo] = __ldg(bg2 + 4 * wy + oo);
        }
        u64c a1[4][NB], a2[4][NB];
#pragma unroll
        for (int oo = 0; oo < 4; oo++)
#pragma unroll
            for (int nb = 0; nb < NB; nb++) { a1[oo][nb] = 0; a2[oo][nb] = 0; }

#pragma unroll
        for (int c4 = 0; c4 < 8; c4++) {
            ulonglong2 xa[NB], xb[NB];
#pragma unroll
            for (int nb = 0; nb < NB; nb++) {
                xa[nb] = *(const ulonglong2*)&S.xq[nb][c4][tx];
                xb[nb] = *(const ulonglong2*)&S.xq[nb][c4][tx + 2];
            }
#pragma unroll
            for (int oo = 0; oo < 4; oo++) {
                int o = 4 * wy + oo;
                ulonglong2 A1 = *(const ulonglong2*)&S.w1a[o][c4];
                ulonglong2 B1 = *(const ulonglong2*)&S.w1b[o][c4];
                ulonglong2 A2 = *(const ulonglong2*)&S.w2a[o][c4];
                ulonglong2 B2 = *(const ulonglong2*)&S.w2b[o][c4];
#pragma unroll
                for (int nb = 0; nb < NB; nb++) {
                    a1[oo][nb] = fma2(xa[nb].x, A1.x, a1[oo][nb]);
                    a1[oo][nb] = fma2(xa[nb].y, A1.y, a1[oo][nb]);
                    a1[oo][nb] = fma2(xb[nb].x, B1.x, a1[oo][nb]);
                    a1[oo][nb] = fma2(xb[nb].y, B1.y, a1[oo][nb]);
                    a2[oo][nb] = fma2(xa[nb].x, A2.x, a2[oo][nb]);
                    a2[oo][nb] = fma2(xa[nb].y, A2.y, a2[oo][nb]);
                    a2[oo][nb] = fma2(xb[nb].x, B2.x, a2[oo][nb]);
                    a2[oo][nb] = fma2(xb[nb].y, B2.y, a2[oo][nb]);
                }
            }
        }

#pragma unroll
        for (int nb = 0; nb < NB; nb++) {
            float4 gq;
#pragma unroll
            for (int oo = 0; oo < 4; oo++) {
                int o = 4 * wy + oo;
                float s1 = f2sum(a1[oo][nb]) + bg1v[oo];
                float s2 = f2sum(a2[oo][nb]) + bg2v[oo];
                float e1 = __expf(2.f * s1);
                float th = 1.f - __fdividef(2.f, e1 + 1.f);    // tanh, inf-safe
                float sg = __fdividef(1.f, 1.f + __expf(-s2)); // sigmoid
                float gated = th * sg;
                out1[((size_t)(b * DC + o) * NN + (n0 + nb)) * TP + tx] = gated;
                (&gq.x)[oo] = gated;
            }
            __half2 h0 = __floats2half2_rn(gq.x, gq.y);
            __half2 h1 = __floats2half2_rn(gq.z, gq.w);
            uint2 hp;
            hp.x = *(unsigned int*)&h0;
            hp.y = *(unsigned int*)&h1;
            *(uint2*)&S.gs[nb][tx * GSP + wy * 2] = hp;
        }
    }
    __syncthreads();

    // ---- phase 2: z[t][o] = sum_d gated[t][d] * Wcomb[o][d]  (fp16 in/out) --
    {
        int o  = tid & 63;
        int ts = tid >> 6;          // 0..3
        ulonglong2 wr[8];
#pragma unroll
        for (int d4 = 0; d4 < 8; d4++)
            wr[d4] = *(const ulonglong2*)&S.wcq[d4][o];
#pragma unroll
        for (int nb = 0; nb < NB; nb++) {
            const unsigned int* gsn = S.gs[nb];
#pragma unroll
            for (int it = 0; it < 8; it++) {
                int t = ts * 8 + it;
                u64c za = 0, zb = 0;
#pragma unroll
                for (int d4 = 0; d4 < 8; d4++) {
                    uint2 gg = *(const uint2*)&gsn[t * GSP + d4 * 2];  // LDS.64 bcast
                    za = fma2(h2tof2(gg.x), wr[d4].x, za);
                    zb = fma2(h2tof2(gg.y), wr[d4].y, zb);
                }
                g_zh[((size_t)(b * TP + t) * NN + (n0 + nb)) * OC + o] =
                    __float2half(f2sum(za) + f2sum(zb));
            }
        }
    }
}

// ---------------- K_spmm: gather over fp16 z, subgroup-per-row --------------
// 512 blocks (one per graph). z slab (1000x64 half = 128 KB) in dynamic SMEM.
// Warp = 4 subgroups x 8 lanes; subgroup walks one row's edge list; lane
// covers 8 channels. CONVERSION-REDUCED inner loop: edge PAIRS multiply in
// fp16 (HMUL2 + HFMA2, 2-term fp16 chain only; v pre-duplicated half2 in CSR),
// then ONE h2tof2 + add2 per pair into fp32 accumulators -> F2F pressure
// halved vs R13 (theory: the invisible cvt pipe binds this kernel).
__global__ __launch_bounds__(1024, 1) void k_spmm(float* __restrict__ y)
{
    extern __shared__ char z_raw[];           // [N][64] halves, 128 B rows
    int g   = blockIdx.x;
    int tid = threadIdx.x;

    {
        const uint4* src = (const uint4*)(g_zh + (size_t)g * NN * OC);
        uint4* dst = (uint4*)z_raw;
        for (int f = tid; f < NN * OC / 8; f += 1024)
            dst[f] = src[f];
    }
    __syncthreads();

    int lane = tid & 31;
    int sub  = (lane >> 3);                   // 0..3 row subgroup
    int l8   = lane & 7;                      // channel octet
    int o0   = l8 * 8;
    int warp = tid >> 5;

    float4 yb0 = *(const float4*)(g_ybias + o0);
    float4 yb1 = *(const float4*)(g_ybias + o0 + 4);
    const char* zb = z_raw + l8 * 16;

    for (int i0 = warp * 4 + sub; i0 < NN + 3; i0 += 128) {
        bool valid = (i0 < NN);
        int r0 = 0, r1 = 0;
        if (valid) { r0 = g_off[i0]; r1 = g_off[i0 + 1]; }

        u64c a0 = pack2(yb0.x, yb0.y);
        u64c a1 = pack2(yb0.z, yb0.w);
        u64c a2 = pack2(yb1.x, yb1.y);
        u64c a3 = pack2(yb1.z, yb1.w);

        int e = r0;
        for (; e + 2 <= r1; e += 2) {
            int2 e0 = __ldg(&g_csr[e]);
            int2 e1 = __ldg(&g_csr[e + 1]);
            uint4 z0 = *(const uint4*)(zb + e0.x);
            uint4 z1 = *(const uint4*)(zb + e1.x);
            unsigned int v0 = (unsigned int)e0.y;   // half2 (v,v)
            unsigned int v1 = (unsigned int)e1.y;
            // fp16 pair products (2-term chains), one convert per pair
            unsigned int p0 = hfma2u(v1, z1.x, hmul2u(v0, z0.x));
            unsigned int p1 = hfma2u(v1, z1.y, hmul2u(v0, z0.y));
            unsigned int p2 = hfma2u(v1, z1.z, hmul2u(v0, z0.z));
            unsigned int p3 = hfma2u(v1, z1.w, hmul2u(v0, z0.w));
            a0 = add2(h2tof2(p0), a0);
            a1 = add2(h2tof2(p1), a1);
            a2 = add2(h2tof2(p2), a2);
            a3 = add2(h2tof2(p3), a3);
        }
        if (e < r1) {                          // odd remainder edge
            int2 ev = __ldg(&g_csr[e]);
            uint4 zz = *(const uint4*)(zb + ev.x);
            unsigned int vv = (unsigned int)ev.y;
            a0 = add2(h2tof2(hmul2u(vv, zz.x)), a0);
            a1 = add2(h2tof2(hmul2u(vv, zz.y)), a1);
            a2 = add2(h2tof2(hmul2u(vv, zz.z)), a2);
            a3 = add2(h2tof2(hmul2u(vv, zz.w)), a3);
        }

        if (valid) {
            float* yo = y + ((size_t)g * NN + i0) * OC + o0;
            float4 r0v, r1v;
            r0v.x = u64lo(a0); r0v.y = u64hi(a0);
            r0v.z = u64lo(a1); r0v.w = u64hi(a1);
            r1v.x = u64lo(a2); r1v.y = u64hi(a2);
            r1v.z = u64lo(a3); r1v.w = u64hi(a3);
            *(float4*)yo       = r0v;
            *(float4*)(yo + 4) = r1v;
        }
    }
}

// ---------------- launcher ----------------
extern "C" void kernel_launch(void* const* d_in, const int* in_sizes, int n_in,
                              void* d_out, int out_size)
{
    const float* x    = (const float*)d_in[0];
    const int*   ei   = (const int*)  d_in[1];
    const float* ew   = (const float*)d_in[2];
    const float* wg1  = (const float*)d_in[3];
    const float* bg1  = (const float*)d_in[4];
    const float* wg2  = (const float*)d_in[5];
    const float* bg2  = (const float*)d_in[6];
    const float* wgcn = (const float*)d_in[7];
    const float* bgcn = (const float*)d_in[8];
    const float* wout = (const float*)d_in[9];
    const float* bout = (const float*)d_in[10];
    float* out = (float*)d_out;

    // 4 launches: k_spmm is launch #4 (ncu capture slot)
    k_comb <<<1, 512>>>(wgcn, bgcn, wout, bout);
    k_build<<<1, 1024>>>(ei, ew);

    size_t gate_smem = sizeof(SmemGate);      // ~51 KB (2 blocks/SM)
    cudaFuncSetAttribute(k_gate, cudaFuncAttributeMaxDynamicSharedMemorySize,
                         (int)gate_smem);
    k_gate<<<BB * (NN / NB), dim3(32, 8), gate_smem>>>(x, wg1, bg1, wg2, bg2, out);

    size_t smem_bytes = (size_t)NN * OC * sizeof(__half);   // 128 KB
    cudaFuncSetAttribute(k_spmm, cudaFuncAttributeMaxDynamicSharedMemorySize,
                         (int)smem_bytes);
    k_spmm<<<GG, 1024, smem_bytes>>>(out + OUT1_ELEMS);
}

// round 17
// speedup vs baseline: 1.2093x; 1.0826x over previous
#include <cuda_runtime.h>
#include <cuda_fp16.h>
#include <cstdint>

// ---------------- problem constants ----------------
#define BB   16
#define TT   34
#define TP   32          // T - DIL
#define NN   1000
#define CIN  32
#define DC   32
#define OC   64
#define EE   16000
#define NNZ  (EE + NN)   // edges + self loops = 17000
#define GG   (BB * TP)   // 512 graphs
#define NB   4           // nodes per k_gate block

#define OUT1_ELEMS ((size_t)BB * DC * NN * TP)        // 16,384,000

typedef unsigned long long u64c;

// ---------------- f32x2 packed helpers ----------------
__device__ __forceinline__ u64c fma2(u64c a, u64c b, u64c c) {
    u64c d;
    asm("fma.rn.f32x2 %0, %1, %2, %3;" : "=l"(d) : "l"(a), "l"(b), "l"(c));
    return d;
}
__device__ __forceinline__ u64c add2(u64c a, u64c b) {
    u64c d;
    asm("add.rn.f32x2 %0, %1, %2;" : "=l"(d) : "l"(a), "l"(b));
    return d;
}
__device__ __forceinline__ float f2sum(u64c a) {
    return __int_as_float((int)(a & 0xffffffffULL)) +
           __int_as_float((int)(a >> 32));
}
__device__ __forceinline__ u64c pack2(float lo, float hi) {
    u64c r;
    asm("mov.b64 %0, {%1, %2};" : "=l"(r) : "f"(lo), "f"(hi));
    return r;
}
__device__ __forceinline__ float u64lo(u64c a) { return __int_as_float((int)(a & 0xffffffffULL)); }
__device__ __forceinline__ float u64hi(u64c a) { return __int_as_float((int)(a >> 32)); }
// half2 (as uint) -> packed f32x2
__device__ __forceinline__ u64c h2tof2(unsigned int h) {
    __half2 hv = *(__half2*)&h;
    float2 f = __half22float2(hv);
    u64c r;
    asm("mov.b64 %0, {%1, %2};" : "=l"(r) : "f"(f.x), "f"(f.y));
    return r;
}
// fp16x2 ops on uint-carried half2
__device__ __forceinline__ unsigned int hmul2u(unsigned int a, unsigned int b) {
    __half2 r = __hmul2(*(__half2*)&a, *(__half2*)&b);
    return *(unsigned int*)&r;
}
__device__ __forceinline__ unsigned int hfma2u(unsigned int a, unsigned int b, unsigned int c) {
    __half2 r = __hfma2(*(__half2*)&a, *(__half2*)&b, *(__half2*)&c);
    return *(unsigned int*)&r;
}

// ---------------- device scratch ----------------
__device__ __half g_zh[(size_t)GG * NN * OC];  // 65.5 MB: z = gated @ Wcomb^T (fp16)
__device__ float  g_wcomb[OC * DC];            // Wcomb[o][d] = sum_c wout[o][c] wgcn[c][d]
__device__ float  g_ybias[OC];                 // bgcn @ wout^T + bout
__device__ int    g_off[NN + 1];
__device__ int2   g_csr[NNZ];                  // (src*128 byte offset, half2(val,val))

// ---------------- K_comb: combined weights + ybias --------------------------
__global__ void k_comb(const float* __restrict__ wgcn, const float* __restrict__ bgcn,
                       const float* __restrict__ wout, const float* __restrict__ bout) {
    __shared__ float sg[CIN * DC];   // wgcn [c][d]
    __shared__ float so[OC * CIN];   // wout [o][c]
    __shared__ float sb[CIN];
    int tid = threadIdx.x;
    for (int f = tid; f < CIN * DC; f += blockDim.x) sg[f] = wgcn[f];
    for (int f = tid; f < OC * CIN; f += blockDim.x) so[f] = wout[f];
    if (tid < CIN) sb[tid] = bgcn[tid];
    __syncthreads();
    for (int f = tid; f < OC * DC; f += blockDim.x) {
        int o = f >> 5, d = f & 31;
        float s = 0.f;
#pragma unroll
        for (int c = 0; c < CIN; c++) s += so[o * CIN + c] * sg[c * DC + d];
        g_wcomb[f] = s;
    }
    if (tid < OC) {
        float s = bout[tid];
#pragma unroll
        for (int c = 0; c < CIN; c++) s += sb[c] * so[tid * CIN + c];
        g_ybias[tid] = s;
    }
}

// ---------------- K_build: fused CSR build (single block, smem atomics) ----
__global__ __launch_bounds__(1024) void k_build(const int* __restrict__ ei,
                                                const float* __restrict__ ew) {
    __shared__ float sdeg[NN];
    __shared__ int   scnt[NN];
    __shared__ int   ssc[1024];
    __shared__ int   scur[NN];
    int tid = threadIdx.x;

    for (int i = tid; i < NN; i += 1024) { sdeg[i] = 0.f; scnt[i] = 0; }
    __syncthreads();

    for (int i = tid; i < NNZ; i += 1024) {
        int d; float w;
        if (i < EE) { d = ei[EE + i]; w = ew[i]; }
        else        { d = i - EE;     w = 1.f;   }
        atomicAdd(&sdeg[d], w);
        atomicAdd(&scnt[d], 1);
    }
    __syncthreads();

    int v = (tid < NN) ? scnt[tid] : 0;
    ssc[tid] = v;
    __syncthreads();
    for (int off = 1; off < 1024; off <<= 1) {
        int tv = (tid >= off) ? ssc[tid - off] : 0;
        __syncthreads();
        ssc[tid] += tv;
        __syncthreads();
    }
    if (tid < NN) {
        int excl = ssc[tid] - v;
        scur[tid] = excl;
        g_off[tid] = excl;
    }
    if (tid == NN - 1) g_off[NN] = ssc[tid];
    __syncthreads();

    for (int i = tid; i < NNZ; i += 1024) {
        int s, d; float w;
        if (i < EE) { s = ei[i]; d = ei[EE + i]; w = ew[i]; }
        else        { s = i - EE; d = s;         w = 1.f;   }
        float degs = sdeg[s], degd = sdeg[d];
        float dis_s = (degs > 0.f) ? rsqrtf(degs) : 0.f;
        float dis_d = (degd > 0.f) ? rsqrtf(degd) : 0.f;
        float nrm = dis_s * w * dis_d;
        int p = atomicAdd(&scur[d], 1);
        // fp16 slab row pitch = 64 ch * 2B = 128 B; val pre-duplicated half2
        __half2 hv = __half2half2(__float2half_rn(nrm));
        g_csr[p] = make_int2(s * 128, *(int*)&hv);
    }
}

// ---------------- K_gate: fused gated conv + z, NB=4 nodes per block -------
// Phase 1: warp wy owns o-quad, t = lane, NB-node weight reuse, fp32 weights,
// packed fma2; gated stored to smem as fp32 float4 (STS.128 conflict-free,
// pitch 36) and to out1 exact fp32. Phase 2: thread (o=tid&63, ts=tid>>6)
// reads gs as LDS.128 broadcasts aliased directly into fma2 operands — ZERO
// conversions (the 512 h2tof2/thread of the fp16-gs variant were cvt-pipe
// pressure, same bottleneck proven in k_spmm R16); fp16 z stores.
// __launch_bounds__(256,2) caps regs at 128 -> 2 blocks/SM.
struct SmemGate {
    float4 xq[NB][8][34];                  // [nb][c4][t]
    float4 w1a[32][8], w1b[32][8];         // [o][c4]
    float4 w2a[32][8], w2b[32][8];
    float4 wcq[8][64];                     // [d4][o] = Wcomb[o][4d4..4d4+3]
    float  gs[NB][32 * 36];                // gated [t][d] fp32, pitch 36
};

__global__ __launch_bounds__(256, 2) void k_gate(
    const float* __restrict__ x,
    const float* __restrict__ wg1, const float* __restrict__ bg1,
    const float* __restrict__ wg2, const float* __restrict__ bg2,
    float* __restrict__ out1)
{
    extern __shared__ char smem_raw[];
    SmemGate& S = *(SmemGate*)smem_raw;

    int blk = blockIdx.x;                  // 4000 blocks
    int b  = blk / (NN / NB);
    int n0 = (blk - b * (NN / NB)) * NB;

    int tx = threadIdx.x;                  // 0..31 (t)
    int wy = threadIdx.y;                  // 0..7  (o-quad)
    int tid = wy * 32 + tx;

    // stage gate weights (flat f = o*32+c, 1024 per array)
    for (int f = tid; f < 32 * 32; f += 256) {
        float2 v1 = *(const float2*)(wg1 + f * 2);
        float2 v2 = *(const float2*)(wg2 + f * 2);
        ((float*)S.w1a)[f] = v1.x;
        ((float*)S.w1b)[f] = v1.y;
        ((float*)S.w2a)[f] = v2.x;
        ((float*)S.w2b)[f] = v2.y;
    }
    // stage Wcomb: flat f = (d4*64+o)*4+k  <-  wcomb[o*32 + d4*4 + k]
    for (int f = tid; f < 8 * 64 * 4; f += 256) {
        int k = f & 3, o = (f >> 2) & 63, d4 = f >> 8;
        ((float*)S.wcq)[f] = g_wcomb[o * 32 + d4 * 4 + k];
    }
    // stage x tiles: NB nodes x 34 t x 8 c4
    for (int f = tid; f < NB * 34 * 8; f += 256) {
        int nb = f / (34 * 8);
        int r  = f - nb * (34 * 8);
        int t = r >> 3, c4 = r & 7;
        S.xq[nb][c4][t] =
            *(const float4*)(x + ((size_t)(b * TT + t) * NN + (n0 + nb)) * CIN + c4 * 4);
    }
    __syncthreads();

    // ---- phase 1: gates ----
    {
        float bg1v[4], bg2v[4];
#pragma unroll
        for (int oo = 0; oo < 4; oo++) {
            bg1v[oo] = __ldg(bg1 + 4 * wy + oo);
            bg2v[oo] = __ldg(bg2 + 4 * wy + oo);
        }
        u64c a1[4][NB], a2[4][NB];
#pragma unroll
        for (int oo = 0; oo < 4; oo++)
#pragma unroll
            for (int nb = 0; nb < NB; nb++) { a1[oo][nb] = 0; a2[oo][nb] = 0; }

#pragma unroll
        for (int c4 = 0; c4 < 8; c4++) {
            ulonglong2 xa[NB], xb[NB];
#pragma unroll
            for (int nb = 0; nb < NB; nb++) {
                xa[nb] = *(const ulonglong2*)&S.xq[nb][c4][tx];
                xb[nb] = *(const ulonglong2*)&S.xq[nb][c4][tx + 2];
            }
#pragma unroll
            for (int oo = 0; oo < 4; oo++) {
                int o = 4 * wy + oo;
                ulonglong2 A1 = *(const ulonglong2*)&S.w1a[o][c4];
                ulonglong2 B1 = *(const ulonglong2*)&S.w1b[o][c4];
                ulonglong2 A2 = *(const ulonglong2*)&S.w2a[o][c4];
                ulonglong2 B2 = *(const ulonglong2*)&S.w2b[o][c4];
#pragma unroll
                for (int nb = 0; nb < NB; nb++) {
                    a1[oo][nb] = fma2(xa[nb].x, A1.x, a1[oo][nb]);
                    a1[oo][nb] = fma2(xa[nb].y, A1.y, a1[oo][nb]);
                    a1[oo][nb] = fma2(xb[nb].x, B1.x, a1[oo][nb]);
                    a1[oo][nb] = fma2(xb[nb].y, B1.y, a1[oo][nb]);
                    a2[oo][nb] = fma2(xa[nb].x, A2.x, a2[oo][nb]);
                    a2[oo][nb] = fma2(xa[nb].y, A2.y, a2[oo][nb]);
                    a2[oo][nb] = fma2(xb[nb].x, B2.x, a2[oo][nb]);
                    a2[oo][nb] = fma2(xb[nb].y, B2.y, a2[oo][nb]);
                }
            }
        }

#pragma unroll
        for (int nb = 0; nb < NB; nb++) {
            float4 gq;
#pragma unroll
            for (int oo = 0; oo < 4; oo++) {
                int o = 4 * wy + oo;
                float s1 = f2sum(a1[oo][nb]) + bg1v[oo];
                float s2 = f2sum(a2[oo][nb]) + bg2v[oo];
                float e1 = __expf(2.f * s1);
                float th = 1.f - __fdividef(2.f, e1 + 1.f);    // tanh, inf-safe
                float sg = __fdividef(1.f, 1.f + __expf(-s2)); // sigmoid
                float gated = th * sg;
                out1[((size_t)(b * DC + o) * NN + (n0 + nb)) * TP + tx] = gated;
                (&gq.x)[oo] = gated;
            }
            *(float4*)&S.gs[nb][tx * 36 + 4 * wy] = gq;   // conflict-free STS.128
        }
    }
    __syncthreads();

    // ---- phase 2: z[t][o] = sum_d gated[t][d] * Wcomb[o][d]  (no cvt) ------
    {
        int o  = tid & 63;
        int ts = tid >> 6;          // 0..3
        ulonglong2 wr[8];
#pragma unroll
        for (int d4 = 0; d4 < 8; d4++)
            wr[d4] = *(const ulonglong2*)&S.wcq[d4][o];
#pragma unroll
        for (int nb = 0; nb < NB; nb++) {
            const float* gsn = S.gs[nb];
#pragma unroll
            for (int it = 0; it < 8; it++) {
                int t = ts * 8 + it;
                const ulonglong2* gp = (const ulonglong2*)(gsn + t * 36);
                u64c za = 0, zb = 0;
#pragma unroll
                for (int d4 = 0; d4 < 8; d4++) {
                    ulonglong2 g2 = gp[d4];            // LDS.128 bcast, no cvt
                    za = fma2(g2.x, wr[d4].x, za);
                    zb = fma2(g2.y, wr[d4].y, zb);
                }
                g_zh[((size_t)(b * TP + t) * NN + (n0 + nb)) * OC + o] =
                    __float2half(f2sum(za) + f2sum(zb));
            }
        }
    }
}

// ---------------- K_spmm: gather over fp16 z, subgroup-per-row --------------
// 512 blocks (one per graph). z slab (1000x64 half = 128 KB) in dynamic SMEM.
// Warp = 4 subgroups x 8 lanes; subgroup walks one row's edge list; lane
// covers 8 channels. Edge QUADS multiply/accumulate in fp16 (4-term HMUL2/
// HFMA2 chains; v pre-duplicated half2 in CSR), then ONE h2tof2 + add2 per
// quad into fp32 accumulators -> cvt pressure 1/4 per edge (cvt pipe proven
// binding in R16).
__global__ __launch_bounds__(1024, 1) void k_spmm(float* __restrict__ y)
{
    extern __shared__ char z_raw[];           // [N][64] halves, 128 B rows
    int g   = blockIdx.x;
    int tid = threadIdx.x;

    {
        const uint4* src = (const uint4*)(g_zh + (size_t)g * NN * OC);
        uint4* dst = (uint4*)z_raw;
        for (int f = tid; f < NN * OC / 8; f += 1024)
            dst[f] = src[f];
    }
    __syncthreads();

    int lane = tid & 31;
    int sub  = (lane >> 3);                   // 0..3 row subgroup
    int l8   = lane & 7;                      // channel octet
    int o0   = l8 * 8;
    int warp = tid >> 5;

    float4 yb0 = *(const float4*)(g_ybias + o0);
    float4 yb1 = *(const float4*)(g_ybias + o0 + 4);
    const char* zb = z_raw + l8 * 16;

    for (int i0 = warp * 4 + sub; i0 < NN + 3; i0 += 128) {
        bool valid = (i0 < NN);
        int r0 = 0, r1 = 0;
        if (valid) { r0 = g_off[i0]; r1 = g_off[i0 + 1]; }

        u64c a0 = pack2(yb0.x, yb0.y);
        u64c a1 = pack2(yb0.z, yb0.w);
        u64c a2 = pack2(yb1.x, yb1.y);
        u64c a3 = pack2(yb1.z, yb1.w);

        int e = r0;
        for (; e + 4 <= r1; e += 4) {
            int2 e0 = __ldg(&g_csr[e]);
            int2 e1 = __ldg(&g_csr[e + 1]);
            int2 e2 = __ldg(&g_csr[e + 2]);
            int2 e3 = __ldg(&g_csr[e + 3]);
            uint4 z0 = *(const uint4*)(zb + e0.x);
            uint4 z1 = *(const uint4*)(zb + e1.x);
            uint4 z2 = *(const uint4*)(zb + e2.x);
            uint4 z3 = *(const uint4*)(zb + e3.x);
            unsigned int v0 = (unsigned int)e0.y;   // half2 (v,v)
            unsigned int v1 = (unsigned int)e1.y;
            unsigned int v2 = (unsigned int)e2.y;
            unsigned int v3 = (unsigned int)e3.y;
            // 4-term fp16 chains, one convert per quad per channel-pair
            unsigned int p0 = hmul2u(v0, z0.x);
            unsigned int p1 = hmul2u(v0, z0.y);
            unsigned int p2 = hmul2u(v0, z0.z);
            unsigned int p3 = hmul2u(v0, z0.w);
            p0 = hfma2u(v1, z1.x, p0);
            p1 = hfma2u(v1, z1.y, p1);
            p2 = hfma2u(v1, z1.z, p2);
            p3 = hfma2u(v1, z1.w, p3);
            p0 = hfma2u(v2, z2.x, p0);
            p1 = hfma2u(v2, z2.y, p1);
            p2 = hfma2u(v2, z2.z, p2);
            p3 = hfma2u(v2, z2.w, p3);
            p0 = hfma2u(v3, z3.x, p0);
            p1 = hfma2u(v3, z3.y, p1);
            p2 = hfma2u(v3, z3.z, p2);
            p3 = hfma2u(v3, z3.w, p3);
            a0 = add2(h2tof2(p0), a0);
            a1 = add2(h2tof2(p1), a1);
            a2 = add2(h2tof2(p2), a2);
            a3 = add2(h2tof2(p3), a3);
        }
        for (; e + 2 <= r1; e += 2) {
            int2 e0 = __ldg(&g_csr[e]);
            int2 e1 = __ldg(&g_csr[e + 1]);
            uint4 z0 = *(const uint4*)(zb + e0.x);
            uint4 z1 = *(const uint4*)(zb + e1.x);
            unsigned int v0 = (unsigned int)e0.y;
            unsigned int v1 = (unsigned int)e1.y;
            unsigned int p0 = hfma2u(v1, z1.x, hmul2u(v0, z0.x));
            unsigned int p1 = hfma2u(v1, z1.y, hmul2u(v0, z0.y));
            unsigned int p2 = hfma2u(v1, z1.z, hmul2u(v0, z0.z));
            unsigned int p3 = hfma2u(v1, z1.w, hmul2u(v0, z0.w));
            a0 = add2(h2tof2(p0), a0);
            a1 = add2(h2tof2(p1), a1);
            a2 = add2(h2tof2(p2), a2);
            a3 = add2(h2tof2(p3), a3);
        }
        if (e < r1) {                          // odd remainder edge
            int2 ev = __ldg(&g_csr[e]);
            uint4 zz = *(const uint4*)(zb + ev.x);
            unsigned int vv = (unsigned int)ev.y;
            a0 = add2(h2tof2(hmul2u(vv, zz.x)), a0);
            a1 = add2(h2tof2(hmul2u(vv, zz.y)), a1);
            a2 = add2(h2tof2(hmul2u(vv, zz.z)), a2);
            a3 = add2(h2tof2(hmul2u(vv, zz.w)), a3);
        }

        if (valid) {
            float* yo = y + ((size_t)g * NN + i0) * OC + o0;
            float4 r0v, r1v;
            r0v.x = u64lo(a0); r0v.y = u64hi(a0);
            r0v.z = u64lo(a1); r0v.w = u64hi(a1);
            r1v.x = u64lo(a2); r1v.y = u64hi(a2);
            r1v.z = u64lo(a3); r1v.w = u64hi(a3);
            *(float4*)yo       = r0v;
            *(float4*)(yo + 4) = r1v;
        }
    }
}

// ---------------- launcher ----------------
extern "C" void kernel_launch(void* const* d_in, const int* in_sizes, int n_in,
                              void* d_out, int out_size)
{
    const float* x    = (const float*)d_in[0];
    const int*   ei   = (const int*)  d_in[1];
    const float* ew   = (const float*)d_in[2];
    const float* wg1  = (const float*)d_in[3];
    const float* bg1  = (const float*)d_in[4];
    const float* wg2  = (const float*)d_in[5];
    const float* bg2  = (const float*)d_in[6];
    const float* wgcn = (const float*)d_in[7];
    const float* bgcn = (const float*)d_in[8];
    const float* wout = (const float*)d_in[9];
    const float* bout = (const float*)d_in[10];
    float* out = (float*)d_out;

    // 4 launches: k_spmm is launch #4 (ncu capture slot)
    k_comb <<<1, 512>>>(wgcn, bgcn, wout, bout);
    k_build<<<1, 1024>>>(ei, ew);

    size_t gate_smem = sizeof(SmemGate);      // ~60 KB (2 blocks/SM)
    cudaFuncSetAttribute(k_gate, cudaFuncAttributeMaxDynamicSharedMemorySize,
                         (int)gate_smem);
    k_gate<<<BB * (NN / NB), dim3(32, 8), gate_smem>>>(x, wg1, bg1, wg2, bg2, out);

    size_t smem_bytes = (size_t)NN * OC * sizeof(__half);   // 128 KB
    cudaFuncSetAttribute(k_spmm, cudaFuncAttributeMaxDynamicSharedMemorySize,
                         (int)smem_bytes);
    k_spmm<<<GG, 1024, smem_bytes>>>(out + OUT1_ELEMS);
}